// round 6
// baseline (speedup 1.0000x reference)
#include <cuda_runtime.h>
#include <math.h>

#define BB 32
#define TT 4096
#define FF 256
#define KSEL 409            // max(1, int(4096*0.1))
#define RPW 8               // rows per warp
#define RPB 64              // rows per block (8 warps)
#define NCHUNK (TT/RPB)     // 64 chunks per batch

__device__ float g_w[BB*TT];
__device__ float g_part[BB*NCHUNK*FF];
__device__ float g_invZ[BB];

// ==== Kernel A: single-pass fused dot + weighted feature sum, registers only ====
// Butterfly reduce leaves the dot in all lanes; each lane computes w and
// accumulates x*w into 8 register accumulators. x read from DRAM exactly once.
__global__ void __launch_bounds__(256) kA(const float* __restrict__ x,
                                          const float* __restrict__ W,
                                          const float* __restrict__ bias) {
    __shared__ float4 sacc[8][64];          // 8 warps x 256 features
    const int c = blockIdx.x, b = blockIdx.y;
    const int tid = threadIdx.x;
    const int warp = tid >> 5, lane = tid & 31;

    const float4* wr = (const float4*)W;
    const float4 w0 = __ldg(&wr[lane]);
    const float4 w1 = __ldg(&wr[lane + 32]);
    const float bias0 = bias[0];

    const int row0 = c * RPB + warp * RPW;                 // within batch b
    const float4* xg = (const float4*)(x + ((size_t)b*TT + row0) * FF);

    float4 ac0 = make_float4(0.f,0.f,0.f,0.f);
    float4 ac1 = make_float4(0.f,0.f,0.f,0.f);
    float wkeep = 0.f;

    #pragma unroll 4
    for (int r = 0; r < RPW; r++) {
        const float4 a0 = xg[(size_t)r*64 + lane];
        const float4 a1 = xg[(size_t)r*64 + 32 + lane];
        float s = a0.x*w0.x + a0.y*w0.y + a0.z*w0.z + a0.w*w0.w
                + a1.x*w1.x + a1.y*w1.y + a1.z*w1.z + a1.w*w1.w;
        #pragma unroll
        for (int o = 16; o; o >>= 1) s += __shfl_xor_sync(0xffffffffu, s, o);
        const float wv = __expf(tanhf(s + bias0) - 1.0f);  // shift by max=1
        if (lane == r) wkeep = wv;
        ac0.x += a0.x*wv; ac0.y += a0.y*wv; ac0.z += a0.z*wv; ac0.w += a0.w*wv;
        ac1.x += a1.x*wv; ac1.y += a1.y*wv; ac1.z += a1.z*wv; ac1.w += a1.w*wv;
    }
    if (lane < RPW) g_w[b*TT + row0 + lane] = wkeep;

    sacc[warp][lane]      = ac0;            // features 4l..4l+3
    sacc[warp][32 + lane] = ac1;            // features 128+4l..+3
    __syncthreads();

    // block-reduce 8 warps -> g_part[b][c][0..255]
    const int f4 = tid & 63, h = tid >> 6;
    if (h == 0) {
        float4 s = sacc[0][f4];
        #pragma unroll
        for (int wdx = 1; wdx < 8; wdx++) {
            float4 t = sacc[wdx][f4];
            s.x += t.x; s.y += t.y; s.z += t.z; s.w += t.w;
        }
        ((float4*)g_part)[((size_t)b*NCHUNK + c)*64 + f4] = s;
    }
}

// ==== Kernel BCD: Z + exact k-th select + compaction + gather + output ====
__global__ void __launch_bounds__(512) kBCD(const float* __restrict__ x,
                                            float* __restrict__ out) {
    __shared__ float    red[512];
    __shared__ unsigned cnt[32];
    __shared__ unsigned wtot[16];
    __shared__ int      idx_sh[KSEL];
    __shared__ float    wv_sh[KSEL];
    __shared__ float4   acc_sh[512];
    const int b = blockIdx.x, tid = threadIdx.x;
    const int lane = tid & 31, wid = tid >> 5;

    unsigned key[8];
    float zsum = 0.f;
    #pragma unroll
    for (int i = 0; i < 8; i++) {
        float w = g_w[b*TT + tid + i*512];
        key[i] = __float_as_uint(w);       // w in (e^-2, 1]: bits order-preserving
        zsum += w;
    }
    red[tid] = zsum;
    if (tid < 32) cnt[tid] = 0;
    __syncthreads();
    #pragma unroll
    for (int o = 256; o; o >>= 1) {
        if (tid < o) red[tid] += red[tid + o];
        __syncthreads();
    }
    const float invZ = 1.0f / red[0];

    // w in (e^-2, 1]: float bits 31,30=0 and 29..25=11111 -> bisect bits 24..0
    unsigned prefix = 0x3E000000u;
    for (int bit = 24; bit >= 0; bit--) {
        const unsigned test = prefix | (1u << bit);
        unsigned c = 0;
        #pragma unroll
        for (int i = 0; i < 8; i++) c += (key[i] >= test);
        c = __reduce_add_sync(0xffffffffu, c);
        if (lane == 0) atomicAdd(&cnt[bit], c);
        __syncthreads();
        if (cnt[bit] >= KSEL) prefix = test;   // unique counter per bit
    }

    // deterministic compaction of (index, weight) into smem
    unsigned tc = 0;
    #pragma unroll
    for (int i = 0; i < 8; i++) tc += (key[i] >= prefix);
    unsigned inc = tc;
    #pragma unroll
    for (int o = 1; o < 32; o <<= 1) {
        unsigned v = __shfl_up_sync(0xffffffffu, inc, o);
        if (lane >= o) inc += v;
    }
    if (lane == 31) wtot[wid] = inc;
    __syncthreads();
    if (tid == 0) {
        unsigned s = 0;
        #pragma unroll
        for (int j = 0; j < 16; j++) { unsigned t = wtot[j]; wtot[j] = s; s += t; }
    }
    __syncthreads();
    unsigned pos = wtot[wid] + inc - tc;
    #pragma unroll
    for (int i = 0; i < 8; i++) {
        if (key[i] >= prefix) {
            if (pos < KSEL) {
                idx_sh[pos] = tid + i*512;
                wv_sh[pos]  = __uint_as_float(key[i]);
            }
            pos++;
        }
    }
    __syncthreads();

    // partial-sum reduce + emphasis gather (float4 over features)
    const int f4 = tid & 63;       // float4 feature group
    const int h  = tid >> 6;       // 0..7 slice
    const float4* part4 = ((const float4*)g_part) + (size_t)b*NCHUNK*64 + f4;
    float4 a = make_float4(0.f,0.f,0.f,0.f);
    #pragma unroll 8
    for (int c = h; c < NCHUNK; c += 8) {
        float4 v = part4[(size_t)c*64];
        a.x += v.x; a.y += v.y; a.z += v.z; a.w += v.w;
    }
    const float4* xb4 = ((const float4*)(x + (size_t)b*TT*FF)) + f4;
    float4 ac = make_float4(0.f,0.f,0.f,0.f);
    #pragma unroll 4
    for (int p = h; p < KSEL; p += 8) {
        const float4 v = xb4[(size_t)idx_sh[p] * 64];
        const float wv = wv_sh[p];
        ac.x += v.x*wv; ac.y += v.y*wv; ac.z += v.z*wv; ac.w += v.w*wv;
    }
    a.x += 0.5f*ac.x; a.y += 0.5f*ac.y; a.z += 0.5f*ac.z; a.w += 0.5f*ac.w;
    acc_sh[tid] = a;
    __syncthreads();
    if (tid < 64) {
        float4 s = acc_sh[tid];
        #pragma unroll
        for (int j = 1; j < 8; j++) {
            float4 t = acc_sh[tid + j*64];
            s.x += t.x; s.y += t.y; s.z += t.z; s.w += t.w;
        }
        s.x *= invZ; s.y *= invZ; s.z *= invZ; s.w *= invZ;
        ((float4*)out)[b*64 + tid] = s;
    }
}

extern "C" void kernel_launch(void* const* d_in, const int* in_sizes, int n_in,
                              void* d_out, int out_size) {
    const float* x    = (const float*)d_in[0];
    const float* W    = (const float*)d_in[1];
    const float* bias = (const float*)d_in[2];
    float* out = (float*)d_out;

    dim3 gA(NCHUNK, BB);
    kA<<<gA, 256>>>(x, W, bias);
    kBCD<<<BB, 512>>>(x, out);
}

// round 7
// speedup vs baseline: 1.1647x; 1.1647x over previous
#include <cuda_runtime.h>
#include <math.h>

#define BB 32
#define TT 4096
#define FF 256
#define KSEL 409            // max(1, int(4096*0.1))
#define RPW 8               // rows per warp in kA
#define RPB 64              // rows per block in kA
#define NCHUNK (TT/RPB)     // 64
#define NS 16               // gather slices per batch
#define TSLICE (TT/NS)      // 256 rows per slice

__device__ float g_w[BB*TT];
__device__ float g_part[BB*NCHUNK*FF];
__device__ float g_corr[BB*NS*FF];
__device__ float g_invZ[BB];

// ==== Kernel A: single-pass fused dot + weighted feature sum (register-only) ====
__global__ void __launch_bounds__(256) kA(const float* __restrict__ x,
                                          const float* __restrict__ W,
                                          const float* __restrict__ bias) {
    __shared__ float4 sacc[8][64];
    const int c = blockIdx.x, b = blockIdx.y;
    const int tid = threadIdx.x;
    const int warp = tid >> 5, lane = tid & 31;

    const float4* wr = (const float4*)W;
    const float4 w0 = __ldg(&wr[lane]);
    const float4 w1 = __ldg(&wr[lane + 32]);
    const float bias0 = bias[0];

    const int row0 = c * RPB + warp * RPW;
    const float4* xg = (const float4*)(x + ((size_t)b*TT + row0) * FF);

    float4 ac0 = make_float4(0.f,0.f,0.f,0.f);
    float4 ac1 = make_float4(0.f,0.f,0.f,0.f);
    float wkeep = 0.f;

    #pragma unroll 4
    for (int r = 0; r < RPW; r++) {
        const float4 a0 = xg[(size_t)r*64 + lane];
        const float4 a1 = xg[(size_t)r*64 + 32 + lane];
        float s = a0.x*w0.x + a0.y*w0.y + a0.z*w0.z + a0.w*w0.w
                + a1.x*w1.x + a1.y*w1.y + a1.z*w1.z + a1.w*w1.w;
        #pragma unroll
        for (int o = 16; o; o >>= 1) s += __shfl_xor_sync(0xffffffffu, s, o);
        const float wv = __expf(tanhf(s + bias0) - 1.0f);  // shift by max=1
        if (lane == r) wkeep = wv;
        ac0.x += a0.x*wv; ac0.y += a0.y*wv; ac0.z += a0.z*wv; ac0.w += a0.w*wv;
        ac1.x += a1.x*wv; ac1.y += a1.y*wv; ac1.z += a1.z*wv; ac1.w += a1.w*wv;
    }
    if (lane < RPW) g_w[b*TT + row0 + lane] = wkeep;

    sacc[warp][lane]      = ac0;
    sacc[warp][32 + lane] = ac1;
    __syncthreads();

    const int f4 = tid & 63, h = tid >> 6;
    if (h == 0) {
        float4 s = sacc[0][f4];
        #pragma unroll
        for (int wdx = 1; wdx < 8; wdx++) {
            float4 t = sacc[wdx][f4];
            s.x += t.x; s.y += t.y; s.z += t.z; s.w += t.w;
        }
        ((float4*)g_part)[((size_t)b*NCHUNK + c)*64 + f4] = s;
    }
}

// ==== Kernel SG: redundant per-batch selection + wide t-sliced gather ====
// grid (NS, BB). Each block recomputes Z + exact k-th threshold for its batch
// (w[b,:] is 16KB, L2-hot; bisection fully parallel across the 512 blocks),
// then gathers emphasis terms for its 256-row slice. No compaction needed.
__global__ void __launch_bounds__(256) kSG(const float* __restrict__ x) {
    __shared__ float    red[256];
    __shared__ unsigned cnt[32];
    __shared__ float    wsh[TSLICE];
    __shared__ float4   acc_sh[256];
    const int s = blockIdx.x, b = blockIdx.y, tid = threadIdx.x;
    const int lane = tid & 31;

    // full-batch keys: 16 per thread
    unsigned key[16];
    float zsum = 0.f;
    #pragma unroll
    for (int i = 0; i < 16; i++) {
        float w = g_w[b*TT + tid + i*256];
        key[i] = __float_as_uint(w);        // w in (e^-2,1]: bits order-preserving
        zsum += w;
    }
    red[tid] = zsum;
    if (tid < 32) cnt[tid] = 0;
    // own slice's w for the gather phase
    wsh[tid] = g_w[b*TT + s*TSLICE + tid];
    __syncthreads();
    #pragma unroll
    for (int o = 128; o; o >>= 1) {
        if (tid < o) red[tid] += red[tid + o];
        __syncthreads();
    }
    if (s == 0 && tid == 0) g_invZ[b] = 1.0f / red[0];

    // w in (e^-2,1]: bits 31,30=0, bits 29..25=11111 -> bisect bits 24..0
    unsigned prefix = 0x3E000000u;
    for (int bit = 24; bit >= 0; bit--) {
        const unsigned test = prefix | (1u << bit);
        unsigned c = 0;
        #pragma unroll
        for (int i = 0; i < 16; i++) c += (key[i] >= test);
        c = __reduce_add_sync(0xffffffffu, c);
        if (lane == 0) atomicAdd(&cnt[bit], c);
        __syncthreads();
        if (cnt[bit] >= KSEL) prefix = test;   // unique counter per bit
    }

    // gather: rows t0+r with bits(w) >= prefix (warp-uniform predicate)
    const int f4 = tid & 63;        // float4 feature group
    const int h  = tid >> 6;        // 0..3 row-phase
    const int t0 = s * TSLICE;
    const float4* xb4 = ((const float4*)(x + (size_t)b*TT*FF)) + f4;
    float4 a = make_float4(0.f,0.f,0.f,0.f);
    #pragma unroll 4
    for (int r = h; r < TSLICE; r += 4) {
        const float wv = wsh[r];
        if (__float_as_uint(wv) >= prefix) {
            const float4 v = xb4[(size_t)(t0 + r) * 64];
            a.x += v.x*wv; a.y += v.y*wv; a.z += v.z*wv; a.w += v.w*wv;
        }
    }
    acc_sh[tid] = a;
    __syncthreads();
    if (h == 0) {
        float4 v = acc_sh[f4];
        #pragma unroll
        for (int j = 1; j < 4; j++) {
            float4 t = acc_sh[j*64 + f4];
            v.x += t.x; v.y += t.y; v.z += t.z; v.w += t.w;
        }
        ((float4*)g_corr)[((size_t)b*NS + s)*64 + f4] = v;
    }
}

// ==== Kernel D: combine + 1/Z -> out [B,1,F] ====
__global__ void __launch_bounds__(256) kD(float* __restrict__ out) {
    const int b = blockIdx.x, f = threadIdx.x;
    float s1 = 0.f, sc = 0.f;
    #pragma unroll 8
    for (int c = 0; c < NCHUNK; c++) s1 += g_part[(b*NCHUNK + c)*FF + f];
    #pragma unroll
    for (int s = 0; s < NS; s++) sc += g_corr[(b*NS + s)*FF + f];
    out[b*FF + f] = (s1 + 0.5f * sc) * g_invZ[b];
}

extern "C" void kernel_launch(void* const* d_in, const int* in_sizes, int n_in,
                              void* d_out, int out_size) {
    const float* x    = (const float*)d_in[0];
    const float* W    = (const float*)d_in[1];
    const float* bias = (const float*)d_in[2];
    float* out = (float*)d_out;

    dim3 gA(NCHUNK, BB);
    kA<<<gA, 256>>>(x, W, bias);
    dim3 gS(NS, BB);
    kSG<<<gS, 256>>>(x);
    kD<<<BB, 256>>>(out);
}